// round 3
// baseline (speedup 1.0000x reference)
#include <cuda_runtime.h>
#include <cuda_bf16.h>

#define TH 512
#define MT 64
#define PITCH 68   // MT + 4, conflict-free strides

// ---------------- device globals (no allocs allowed) ----------------
__device__ float g_scores[8 * 4096];
__device__ float g_probs[8 * 4096];

// ---------------- f32x2 helpers (sm_103a packed fp32 FMA) ----------------
__device__ __forceinline__ unsigned long long pk2(float a, float b) {
    unsigned long long r;
    asm("mov.b64 %0, {%1,%2};" : "=l"(r) : "f"(a), "f"(b));
    return r;
}
__device__ __forceinline__ void upk2(unsigned long long v, float& a, float& b) {
    asm("mov.b64 {%0,%1}, %2;" : "=f"(a), "=f"(b) : "l"(v));
}
__device__ __forceinline__ unsigned long long fma2(unsigned long long a,
                                                   unsigned long long b,
                                                   unsigned long long c) {
    unsigned long long d;
    asm("fma.rn.f32x2 %0, %1, %2, %3;" : "=l"(d) : "l"(a), "l"(b), "l"(c));
    return d;
}

// ---------------- row-wise instance norm over 256 dims ----------------
// X layout: X[k*PITCH + r], k in [0,256), r in [0,64)
__device__ __forceinline__ void rownorm(float* X, float* red1, float* red2,
                                        float* rowM, float* rowR, int tid) {
    int r = tid & 63, part = tid >> 6;  // 8 parts x 64 rows
    float s1 = 0.f, s2 = 0.f;
    const float* base = X + (part * 32) * PITCH + r;
#pragma unroll
    for (int g = 0; g < 32; g++) {
        float v = base[g * PITCH];
        s1 += v;
        s2 += v * v;
    }
    red1[part * 64 + r] = s1;
    red2[part * 64 + r] = s2;
    __syncthreads();
    if (tid < 64) {
        float a = 0.f, bq = 0.f;
#pragma unroll
        for (int p = 0; p < 8; p++) {
            a += red1[p * 64 + tid];
            bq += red2[p * 64 + tid];
        }
        float m = a * (1.f / 256.f);
        float var = bq * (1.f / 256.f) - m * m;
        rowM[tid] = m;
        rowR[tid] = rsqrtf(var + 1e-5f);
    }
    __syncthreads();
    for (int idx = tid; idx < 256 * 64; idx += TH) {
        int c = idx >> 6, rr = idx & 63;
        float* p = X + c * PITCH + rr;
        *p = (*p - rowM[rr]) * rowR[rr];
    }
    __syncthreads();
}

// ---------------- tiled GEMM: Y[r][c] = act( sum_k X[k][r]*W[k][c] + b[c] ) ----------------
// src/dst col-major (PITCH). Double-buffered 16-row W tiles.
// Thread map: tr = tid>>6 (rows 8*tr..8*tr+7), tc = tid&63 (cols tc+64c).
// acc packed along ROW pairs -> X loads are natural LDS.128 reg-pairs (0 MOV),
// W is scalar LDS.32 + 1 MOV dup. Halves smem crossbar traffic vs col-pairs.
__device__ __forceinline__ void mlp_gemm(const float* __restrict__ src,
                                         float* __restrict__ dst,
                                         const float* __restrict__ Wg,
                                         const float* __restrict__ bias,
                                         float* W0, float* W1, int Krows,
                                         int Ktiles, int act, int tid) {
    int tr = tid >> 6;  // 0..7
    int tc = tid & 63;
    unsigned long long acc[4][4];
#pragma unroll
    for (int i = 0; i < 4; i++)
#pragma unroll
        for (int c = 0; c < 4; c++) acc[i][c] = 0ull;

    const float4* W4 = (const float4*)Wg;
    float4 stg[2];

    // prologue: tile0 -> W0, prefetch tile1 to regs
#pragma unroll
    for (int i = 0; i < 2; i++) {
        int f4i = tid + TH * i;
        int row = (f4i >> 6);
        stg[i] = make_float4(0.f, 0.f, 0.f, 0.f);
        if (row < Krows) stg[i] = W4[row * 64 + (f4i & 63)];
    }
#pragma unroll
    for (int i = 0; i < 2; i++) ((float4*)W0)[tid + TH * i] = stg[i];
    if (Ktiles > 1) {
#pragma unroll
        for (int i = 0; i < 2; i++) {
            int f4i = tid + TH * i;
            int row = (f4i >> 6) + 16;
            stg[i] = make_float4(0.f, 0.f, 0.f, 0.f);
            if (row < Krows) stg[i] = W4[row * 64 + (f4i & 63)];
        }
    }
    __syncthreads();

    for (int kt = 0; kt < Ktiles; kt++) {
        float* cur = (kt & 1) ? W1 : W0;
        float* nxt = (kt & 1) ? W0 : W1;
        if (kt + 1 < Ktiles) {
            // stage tile kt+1 into the other buffer
#pragma unroll
            for (int i = 0; i < 2; i++) ((float4*)nxt)[tid + TH * i] = stg[i];
            if (kt + 2 < Ktiles) {
#pragma unroll
                for (int i = 0; i < 2; i++) {
                    int f4i = tid + TH * i;
                    int row = (f4i >> 6) + (kt + 2) * 16;
                    stg[i] = make_float4(0.f, 0.f, 0.f, 0.f);
                    if (row < Krows) stg[i] = W4[row * 64 + (f4i & 63)];
                }
            }
        }
        const float* xbase = src + (kt * 16) * PITCH + 8 * tr;
#pragma unroll
        for (int k = 0; k < 16; k++) {
            float4 xa = *(const float4*)(xbase + k * PITCH);
            float4 xb = *(const float4*)(xbase + k * PITCH + 4);
            unsigned long long xp0 = pk2(xa.x, xa.y);
            unsigned long long xp1 = pk2(xa.z, xa.w);
            unsigned long long xp2 = pk2(xb.x, xb.y);
            unsigned long long xp3 = pk2(xb.z, xb.w);
            const float* wr = cur + k * 256 + tc;
#pragma unroll
            for (int c = 0; c < 4; c++) {
                float w = wr[64 * c];
                unsigned long long wd = pk2(w, w);
                acc[0][c] = fma2(xp0, wd, acc[0][c]);
                acc[1][c] = fma2(xp1, wd, acc[1][c]);
                acc[2][c] = fma2(xp2, wd, acc[2][c]);
                acc[3][c] = fma2(xp3, wd, acc[3][c]);
            }
        }
        __syncthreads();
    }

    // epilogue: bias + activation + store (rows contiguous -> float4)
#pragma unroll
    for (int c = 0; c < 4; c++) {
        int col = tc + 64 * c;
        float bb = __ldg(bias + col);
        float y[8];
#pragma unroll
        for (int rp = 0; rp < 4; rp++) {
            float lo, hi;
            upk2(acc[rp][c], lo, hi);
            lo += bb;
            hi += bb;
            if (act == 0) {
                lo = fmaxf(lo, 0.f);
                hi = fmaxf(hi, 0.f);
            } else {
                lo = (lo > 0.f) ? lo : 0.01f * lo;
                hi = (hi > 0.f) ? hi : 0.01f * hi;
            }
            y[2 * rp] = lo;
            y[2 * rp + 1] = hi;
        }
        float* dcol = dst + col * PITCH + 8 * tr;
        *(float4*)dcol = make_float4(y[0], y[1], y[2], y[3]);
        *(float4*)(dcol + 4) = make_float4(y[4], y[5], y[6], y[7]);
    }
    __syncthreads();
}

// ---------------- main fused kernel: one CTA = 64 subset rows of one batch ----------------
__global__ void __launch_bounds__(TH, 1)
fused_main(const float* __restrict__ vf, const float* __restrict__ vmask,
           const float* __restrict__ eoh_g, const int* __restrict__ subs,
           const float* __restrict__ cW, const float* __restrict__ cB,
           const float* __restrict__ w1, const float* __restrict__ b1,
           const float* __restrict__ w2a, const float* __restrict__ b2a,
           const float* __restrict__ w2b, const float* __restrict__ b2b,
           const float* __restrict__ sW, const float* __restrict__ sB) {
    extern __shared__ float sm[];
    float* XA = sm;                 // 384*68 = 26112 floats
    float* XB = sm + 26112;         // 256*68 = 17408
    float* W0 = sm + 43520;         // 16*256 = 4096
    float* W1 = sm + 47616;         // 16*256 = 4096
    float* red1 = sm + 51712;       // 512
    float* red2 = sm + 52224;       // 512
    float* rowM = sm + 52736;       // 64
    float* rowR = sm + 52800;       // 64
    float* invs = sm + 52864;       // 64
    float* maskv = sm + 52928;      // 48
    float* eoh = sm + 52976;        // 240  -> total 53216 floats

    int tid = threadIdx.x;
    int b = blockIdx.x >> 6;          // 64 tiles per batch
    int s0 = (blockIdx.x & 63) * MT;

    float* MV = XB;   // alias: masked vert feat [48][256]
    float* SUB = W0;  // alias: subset tile [64][48] (3072 <= 8192 of W0+W1)

    // ---- stage B loads ----
    for (int idx = tid; idx < 48 * 256; idx += TH) {
        int a = idx >> 8;
        float m = vmask[b * 48 + a];
        MV[idx] = vf[(b * 48 + a) * 256 + (idx & 255)] * m * m;  // vf*m * m
    }
    for (int idx = tid; idx < MT * 48; idx += TH) {
        int r = idx / 48, a = idx - r * 48;
        SUB[idx] = (float)subs[(b * 4096 + s0 + r) * 48 + a];
    }
    if (tid < 48) maskv[tid] = vmask[b * 48 + tid];
    if (tid < 240) eoh[tid] = eoh_g[b * 240 + tid];
    __syncthreads();

    // ---- subset-weighted sums: each thread owns one g column, 32 rows ----
    int g = tid & 255, half = tid >> 8;
    int r0 = half * 32;
    float accv[32];
#pragma unroll
    for (int i = 0; i < 32; i++) accv[i] = 0.f;
    for (int a = 0; a < 48; a++) {
        float mva = MV[a * 256 + g];
        const float* sr = SUB + r0 * 48 + a;
#pragma unroll
        for (int i = 0; i < 32; i++) accv[i] += mva * sr[i * 48];
    }
    // ---- per-row size / element counts / thermometer one-hot / zero pad ----
    if (tid < MT) {
        int r = tid;
        float sz = 0.f;
        float c0 = 0.f, c1 = 0.f, c2 = 0.f, c3 = 0.f, c4 = 0.f;
        for (int a = 0; a < 48; a++) {
            float s = SUB[r * 48 + a];
            sz += s * maskv[a];
            c0 += s * eoh[a * 5 + 0];
            c1 += s * eoh[a * 5 + 1];
            c2 += s * eoh[a * 5 + 2];
            c3 += s * eoh[a * 5 + 3];
            c4 += s * eoh[a * 5 + 4];
        }
        invs[r] = 1.f / (sz + 1e-4f);
        float cnt[5] = {c0, c1, c2, c3, c4};
#pragma unroll
        for (int e = 0; e < 5; e++)
            for (int j = 0; j < 20; j++)
                XA[(e * 20 + j) * PITCH + r] = ((float)j < cnt[e]) ? 1.f : 0.f;
        for (int j = 356; j < 384; j++) XA[j * PITCH + r] = 0.f;  // K padding
    }
    __syncthreads();
    // ---- mean feat into XA rows 100..355 ----
    {
        float* dstc = XA + (100 + g) * PITCH;
#pragma unroll
        for (int i = 0; i < 32; i++) dstc[r0 + i] = accv[i] * invs[r0 + i];
    }
    __syncthreads();

    rownorm(XA + 100 * PITCH, red1, red2, rowM, rowR, tid);               // subset_weighted_norm
    mlp_gemm(XA, XB, cW, cB, W0, W1, 356, 23, 0, tid);                    // combine + relu
    rownorm(XB, red1, red2, rowM, rowR, tid);                             // norm_post_combine
    mlp_gemm(XB, XA, w1, b1, W0, W1, 256, 16, 0, tid);                    // l1 + relu
    mlp_gemm(XA, XB, w2a, b2a, W0, W1, 256, 16, 1, tid);                  // l2a + leaky
    mlp_gemm(XB, XA, w2b, b2b, W0, W1, 256, 16, 0, tid);                  // l2b: leaky+relu == relu
    rownorm(XA, red1, red2, rowM, rowR, tid);                             // norm_pre_score

    // ---- score head ----
    {
        int r = tid & 63, part = tid >> 6;
        float s = 0.f;
#pragma unroll
        for (int gg = 0; gg < 32; gg++)
            s += XA[(part * 32 + gg) * PITCH + r] * sW[part * 32 + gg];
        red1[part * 64 + r] = s;
        __syncthreads();
        if (tid < 64) {
            float t = 0.f;
#pragma unroll
            for (int p = 0; p < 8; p++) t += red1[p * 64 + tid];
            g_scores[b * 4096 + s0 + tid] = t + sB[0];
        }
    }
}

// ---------------- per-batch softmax over 4096 scores ----------------
__global__ void softmax_kernel(float* __restrict__ probs_out) {
    __shared__ float sbuf[32];
    __shared__ float sval;
    int b = blockIdx.x, t = threadIdx.x, lane = t & 31, wid = t >> 5;
    const float* sc = g_scores + b * 4096;
    float v0 = sc[t], v1 = sc[t + 1024], v2 = sc[t + 2048], v3 = sc[t + 3072];
    float mx = fmaxf(fmaxf(v0, v1), fmaxf(v2, v3));
#pragma unroll
    for (int o = 16; o; o >>= 1) mx = fmaxf(mx, __shfl_xor_sync(0xffffffffu, mx, o));
    if (lane == 0) sbuf[wid] = mx;
    __syncthreads();
    if (t < 32) {
        float m = sbuf[t];
#pragma unroll
        for (int o = 16; o; o >>= 1) m = fmaxf(m, __shfl_xor_sync(0xffffffffu, m, o));
        if (t == 0) sval = m;
    }
    __syncthreads();
    mx = sval;
    float e0 = expf(v0 - mx), e1 = expf(v1 - mx), e2 = expf(v2 - mx), e3 = expf(v3 - mx);
    float sum = e0 + e1 + e2 + e3;
#pragma unroll
    for (int o = 16; o; o >>= 1) sum += __shfl_xor_sync(0xffffffffu, sum, o);
    __syncthreads();
    if (lane == 0) sbuf[wid] = sum;
    __syncthreads();
    if (t < 32) {
        float s = sbuf[t];
#pragma unroll
        for (int o = 16; o; o >>= 1) s += __shfl_xor_sync(0xffffffffu, s, o);
        if (t == 0) sval = s;
    }
    __syncthreads();
    float inv = 1.f / sval;
    float p0 = e0 * inv, p1 = e1 * inv, p2 = e2 * inv, p3 = e3 * inv;
    probs_out[b * 4096 + t] = p0;
    probs_out[b * 4096 + t + 1024] = p1;
    probs_out[b * 4096 + t + 2048] = p2;
    probs_out[b * 4096 + t + 3072] = p3;
    g_probs[b * 4096 + t] = p0;
    g_probs[b * 4096 + t + 1024] = p1;
    g_probs[b * 4096 + t + 2048] = p2;
    g_probs[b * 4096 + t + 3072] = p3;
}

// ---------------- zero + scatter into spectral bins ----------------
__global__ void zero_kernel(float* __restrict__ p, int n) {
    int idx = blockIdx.x * blockDim.x + threadIdx.x;
    if (idx < n) p[idx] = 0.f;
}

__global__ void scatter_kernel(const int* __restrict__ midx,
                               const float* __restrict__ inten,
                               float* __restrict__ spect) {
    int idx = blockIdx.x * blockDim.x + threadIdx.x;
    if (idx >= 8 * 4096 * 32) return;
    int b = idx >> 17;              // 4096*32 = 131072
    int s = (idx >> 5) & 4095;
    float w = inten[idx] * g_probs[b * 4096 + s];
    atomicAdd(spect + b * 65536 + midx[idx], w);
}

// ---------------- launch ----------------
extern "C" void kernel_launch(void* const* d_in, const int* in_sizes, int n_in,
                              void* d_out, int out_size) {
    const float* vf    = (const float*)d_in[0];
    const float* vmask = (const float*)d_in[1];
    const float* eoh   = (const float*)d_in[2];
    const int*   subs  = (const int*)d_in[4];
    const int*   midx  = (const int*)d_in[6];
    const float* inten = (const float*)d_in[7];
    const float* cW    = (const float*)d_in[8];
    const float* cB    = (const float*)d_in[9];
    const float* w1    = (const float*)d_in[10];
    const float* b1    = (const float*)d_in[11];
    const float* w2a   = (const float*)d_in[12];
    const float* b2a   = (const float*)d_in[13];
    const float* w2b   = (const float*)d_in[14];
    const float* b2b   = (const float*)d_in[15];
    const float* sW    = (const float*)d_in[16];
    const float* sB    = (const float*)d_in[17];
    float* out = (float*)d_out;

    int pOff = out_size - 8 * 4096;  // spect first, probs second
    size_t smem = (size_t)53216 * sizeof(float);
    cudaFuncSetAttribute(fused_main, cudaFuncAttributeMaxDynamicSharedMemorySize,
                         (int)smem);

    zero_kernel<<<(pOff + 511) / 512, 512>>>(out, pOff);
    fused_main<<<512, TH, smem>>>(vf, vmask, eoh, subs, cW, cB, w1, b1, w2a, b2a,
                                  w2b, b2b, sW, sB);
    softmax_kernel<<<8, 1024>>>(out + pOff);
    scatter_kernel<<<2048, 512>>>(midx, inten, out);
}

// round 4
// speedup vs baseline: 1.1716x; 1.1716x over previous
#include <cuda_runtime.h>
#include <cuda_bf16.h>

#define TH 256
#define MT 32
#define PITCH 36    // 32 + 4: conflict-free, 144B col stride (16B aligned)
#define SUBP 49     // raw subset tile stride (odd -> conflict-free)

// ---------------- device globals (no allocs allowed) ----------------
__device__ float g_scores[8 * 4096];
__device__ float g_probs[8 * 4096];

typedef unsigned long long ull;

// ---------------- f32x2 helpers (sm_103a packed fp32 FMA) ----------------
__device__ __forceinline__ ull pk2(float a, float b) {
    ull r;
    asm("mov.b64 %0, {%1,%2};" : "=l"(r) : "f"(a), "f"(b));
    return r;
}
__device__ __forceinline__ void upk2(ull v, float& a, float& b) {
    asm("mov.b64 {%0,%1}, %2;" : "=f"(a), "=f"(b) : "l"(v));
}
__device__ __forceinline__ ull fma2(ull a, ull b, ull c) {
    ull d;
    asm("fma.rn.f32x2 %0, %1, %2, %3;" : "=l"(d) : "l"(a), "l"(b), "l"(c));
    return d;
}

// ---------------- row-wise instance norm over 256 dims, 32 rows ----------------
// X layout: X[k*PITCH + r], k in [0,256), r in [0,32)
__device__ __forceinline__ void rownorm(float* X, float* red1, float* red2,
                                        float* rowM, float* rowR, int tid) {
    int r = tid & 31, part = tid >> 5;  // 8 parts x 32 cols
    float s1 = 0.f, s2 = 0.f;
    const float* base = X + (part * 32) * PITCH + r;
#pragma unroll
    for (int g = 0; g < 32; g++) {
        float v = base[g * PITCH];
        s1 += v;
        s2 += v * v;
    }
    red1[part * 32 + r] = s1;
    red2[part * 32 + r] = s2;
    __syncthreads();
    if (tid < 32) {
        float a = 0.f, bq = 0.f;
#pragma unroll
        for (int p = 0; p < 8; p++) {
            a += red1[p * 32 + tid];
            bq += red2[p * 32 + tid];
        }
        float m = a * (1.f / 256.f);
        float var = bq * (1.f / 256.f) - m * m;
        rowM[tid] = m;
        rowR[tid] = rsqrtf(var + 1e-5f);
    }
    __syncthreads();
#pragma unroll
    for (int i = 0; i < 32; i++) {
        int c = (tid >> 5) + i * 8, rr = tid & 31;
        float* p = X + c * PITCH + rr;
        *p = (*p - rowM[rr]) * rowR[rr];
    }
    __syncthreads();
}

// ---------------- tiled GEMM: Y[r][c] = act( sum_k X[k][r]*W[k][c] + b[c] ) ----------------
// src/dst col-major (PITCH). Double-buffered 8-row W tiles streamed from global.
// tr = tid>>6 (rows 8*tr..8*tr+7), tc = tid&63 (cols tc+64c).
// acc packed along ROW pairs: X via LDS.128 (warp-broadcast), W scalar LDS.32.
// act: 0=relu+bias, 1=leaky(0.01)+bias, 2=scale by invs[row] (no bias/act)
__device__ __forceinline__ void mlp_gemm(const float* __restrict__ src,
                                         float* __restrict__ dst,
                                         const float* __restrict__ Wg,
                                         const float* __restrict__ bias,
                                         const float* __restrict__ invs,
                                         float* W0, float* W1, int Krows,
                                         int Ktiles, int act, int tid) {
    int tr = tid >> 6;  // 0..3
    int tc = tid & 63;
    ull acc[4][4];
#pragma unroll
    for (int i = 0; i < 4; i++)
#pragma unroll
        for (int c = 0; c < 4; c++) acc[i][c] = 0ull;

    const float4* W4 = (const float4*)Wg;
    float4 stg[2];

    // prologue: tile0 -> W0, prefetch tile1 -> regs
#pragma unroll
    for (int i = 0; i < 2; i++) {
        int f4i = tid + TH * i;
        int row = f4i >> 6;
        stg[i] = make_float4(0.f, 0.f, 0.f, 0.f);
        if (row < Krows) stg[i] = W4[row * 64 + (f4i & 63)];
    }
#pragma unroll
    for (int i = 0; i < 2; i++) ((float4*)W0)[tid + TH * i] = stg[i];
    if (Ktiles > 1) {
#pragma unroll
        for (int i = 0; i < 2; i++) {
            int f4i = tid + TH * i;
            int row = (f4i >> 6) + 8;
            stg[i] = make_float4(0.f, 0.f, 0.f, 0.f);
            if (row < Krows) stg[i] = W4[row * 64 + (f4i & 63)];
        }
    }
    __syncthreads();

    for (int kt = 0; kt < Ktiles; kt++) {
        float* cur = (kt & 1) ? W1 : W0;
        float* nxt = (kt & 1) ? W0 : W1;
        if (kt + 1 < Ktiles) {
#pragma unroll
            for (int i = 0; i < 2; i++) ((float4*)nxt)[tid + TH * i] = stg[i];
            if (kt + 2 < Ktiles) {
#pragma unroll
                for (int i = 0; i < 2; i++) {
                    int f4i = tid + TH * i;
                    int row = (f4i >> 6) + (kt + 2) * 8;
                    stg[i] = make_float4(0.f, 0.f, 0.f, 0.f);
                    if (row < Krows) stg[i] = W4[row * 64 + (f4i & 63)];
                }
            }
        }
        const float* xbase = src + (kt * 8) * PITCH + 8 * tr;
#pragma unroll
        for (int k = 0; k < 8; k++) {
            float4 xa = *(const float4*)(xbase + k * PITCH);
            float4 xb = *(const float4*)(xbase + k * PITCH + 4);
            ull xp0 = pk2(xa.x, xa.y);
            ull xp1 = pk2(xa.z, xa.w);
            ull xp2 = pk2(xb.x, xb.y);
            ull xp3 = pk2(xb.z, xb.w);
            const float* wr = cur + k * 256 + tc;
#pragma unroll
            for (int c = 0; c < 4; c++) {
                float w = wr[64 * c];
                ull wd = pk2(w, w);
                acc[0][c] = fma2(xp0, wd, acc[0][c]);
                acc[1][c] = fma2(xp1, wd, acc[1][c]);
                acc[2][c] = fma2(xp2, wd, acc[2][c]);
                acc[3][c] = fma2(xp3, wd, acc[3][c]);
            }
        }
        __syncthreads();
    }

    // epilogue
#pragma unroll
    for (int c = 0; c < 4; c++) {
        int col = tc + 64 * c;
        float y[8];
        if (act == 2) {
#pragma unroll
            for (int rp = 0; rp < 4; rp++) {
                float lo, hi;
                upk2(acc[rp][c], lo, hi);
                y[2 * rp] = lo * invs[8 * tr + 2 * rp];
                y[2 * rp + 1] = hi * invs[8 * tr + 2 * rp + 1];
            }
        } else {
            float bb = __ldg(bias + col);
#pragma unroll
            for (int rp = 0; rp < 4; rp++) {
                float lo, hi;
                upk2(acc[rp][c], lo, hi);
                lo += bb;
                hi += bb;
                if (act == 0) {
                    lo = fmaxf(lo, 0.f);
                    hi = fmaxf(hi, 0.f);
                } else {
                    lo = (lo > 0.f) ? lo : 0.01f * lo;
                    hi = (hi > 0.f) ? hi : 0.01f * hi;
                }
                y[2 * rp] = lo;
                y[2 * rp + 1] = hi;
            }
        }
        float* dcol = dst + col * PITCH + 8 * tr;
        *(float4*)dcol = make_float4(y[0], y[1], y[2], y[3]);
        *(float4*)(dcol + 4) = make_float4(y[4], y[5], y[6], y[7]);
    }
    __syncthreads();
}

// ---------------- main fused kernel: one CTA = 32 subset rows of one batch ----------------
__global__ void __launch_bounds__(TH, 2)
fused_main(const float* __restrict__ vf, const float* __restrict__ vmask,
           const float* __restrict__ eoh_g, const int* __restrict__ subs,
           const float* __restrict__ cW, const float* __restrict__ cB,
           const float* __restrict__ w1, const float* __restrict__ b1,
           const float* __restrict__ w2a, const float* __restrict__ b2a,
           const float* __restrict__ w2b, const float* __restrict__ b2b,
           const float* __restrict__ sW, const float* __restrict__ sB) {
    extern __shared__ float sm[];
    float* XA = sm;                  // 360*36 = 12960 floats
    float* XB = sm + 12960;          // 256*36 = 9216
    float* W0 = sm + 22176;          // 8*256 = 2048
    float* W1 = sm + 24224;          // 8*256 = 2048
    float* red1 = sm + 26272;        // 256
    float* red2 = sm + 26528;        // 256
    float* rowM = sm + 26784;        // 32
    float* rowR = sm + 26816;        // 32
    float* invs = sm + 26848;        // 32
    float* maskv = sm + 26880;       // 48
    float* eoh = sm + 26928;         // 240  -> total 27168 floats (106.1 KB)

    int tid = threadIdx.x;
    int b = blockIdx.x >> 7;           // 128 tiles per batch
    int s0 = (blockIdx.x & 127) * MT;

    float* SUBR = W0;  // alias: raw subset tile [32][SUBP] = 1568 <= 4096 (W0+W1)

    // ---- loads: raw subsets (contiguous 1536 ints), mask, element one-hot ----
    for (int idx = tid; idx < MT * 48; idx += TH) {
        int r = idx / 48, a = idx - r * 48;
        SUBR[r * SUBP + a] = (float)subs[(b * 4096 + s0) * 48 + idx];
    }
    if (tid < 48) maskv[tid] = vmask[b * 48 + tid];
    if (tid < 240) eoh[tid] = eoh_g[b * 240 + tid];
    __syncthreads();

    // ---- counts (160 thr), subset size (32 thr) ----
    if (tid < 160) {
        int r = tid / 5, e = tid - 5 * (tid / 5);
        float c = 0.f;
        for (int a = 0; a < 48; a++) c += SUBR[r * SUBP + a] * eoh[a * 5 + e];
        red2[tid] = c;
    } else if (tid < 192) {
        int r = tid - 160;
        float sz = 0.f;
        for (int a = 0; a < 48; a++) sz += SUBR[r * SUBP + a] * maskv[a];
        invs[r] = 1.f / (sz + 1e-4f);
    }
    __syncthreads();

    // ---- thermometer rows 0..99 ; X = (s * m^2) k-major into XB ; zero pad rows ----
    if (tid < 32) {
        int r = tid;
        float cnt[5];
#pragma unroll
        for (int e = 0; e < 5; e++) cnt[e] = red2[r * 5 + e];
#pragma unroll
        for (int e = 0; e < 5; e++)
            for (int j = 0; j < 20; j++)
                XA[(e * 20 + j) * PITCH + r] = ((float)j < cnt[e]) ? 1.f : 0.f;
    }
    for (int idx = tid; idx < 48 * 32; idx += TH) {
        int a = idx >> 5, r = idx & 31;
        float m = maskv[a];
        XB[a * PITCH + r] = SUBR[r * SUBP + a] * m * m;
    }
    if (tid >= 128 && tid < 256) {  // zero K-pad rows 356..359
        int rr = (tid - 128) & 31, row = 356 + ((tid - 128) >> 5);
        XA[row * PITCH + rr] = 0.f;
    }
    __syncthreads();

    // ---- stage A as GEMM: meanfeat = (X^T @ vf_b) * invs  -> XA rows 100..355 ----
    mlp_gemm(XB, XA + 100 * PITCH, vf + b * 48 * 256, 0, invs, W0, W1, 48, 6, 2, tid);

    rownorm(XA + 100 * PITCH, red1, red2, rowM, rowR, tid);                // subset_weighted_norm
    mlp_gemm(XA, XB, cW, cB, 0, W0, W1, 356, 45, 0, tid);                  // combine + relu
    rownorm(XB, red1, red2, rowM, rowR, tid);                              // norm_post_combine
    mlp_gemm(XB, XA, w1, b1, 0, W0, W1, 256, 32, 0, tid);                  // l1 + relu
    mlp_gemm(XA, XB, w2a, b2a, 0, W0, W1, 256, 32, 1, tid);                // l2a + leaky
    mlp_gemm(XB, XA, w2b, b2b, 0, W0, W1, 256, 32, 0, tid);                // l2b: leaky+relu == relu
    rownorm(XA, red1, red2, rowM, rowR, tid);                              // norm_pre_score

    // ---- score head ----
    {
        int r = tid & 31, part = tid >> 5;
        float s = 0.f;
#pragma unroll
        for (int gg = 0; gg < 32; gg++)
            s += XA[(part * 32 + gg) * PITCH + r] * sW[part * 32 + gg];
        red1[part * 32 + r] = s;
        __syncthreads();
        if (tid < 32) {
            float t = 0.f;
#pragma unroll
            for (int p = 0; p < 8; p++) t += red1[p * 32 + tid];
            g_scores[b * 4096 + s0 + tid] = t + sB[0];
        }
    }
}

// ---------------- per-batch softmax over 4096 scores ----------------
__global__ void softmax_kernel(float* __restrict__ probs_out) {
    __shared__ float sbuf[32];
    __shared__ float sval;
    int b = blockIdx.x, t = threadIdx.x, lane = t & 31, wid = t >> 5;
    const float* sc = g_scores + b * 4096;
    float v0 = sc[t], v1 = sc[t + 1024], v2 = sc[t + 2048], v3 = sc[t + 3072];
    float mx = fmaxf(fmaxf(v0, v1), fmaxf(v2, v3));
#pragma unroll
    for (int o = 16; o; o >>= 1) mx = fmaxf(mx, __shfl_xor_sync(0xffffffffu, mx, o));
    if (lane == 0) sbuf[wid] = mx;
    __syncthreads();
    if (t < 32) {
        float m = sbuf[t];
#pragma unroll
        for (int o = 16; o; o >>= 1) m = fmaxf(m, __shfl_xor_sync(0xffffffffu, m, o));
        if (t == 0) sval = m;
    }
    __syncthreads();
    mx = sval;
    float e0 = expf(v0 - mx), e1 = expf(v1 - mx), e2 = expf(v2 - mx), e3 = expf(v3 - mx);
    float sum = e0 + e1 + e2 + e3;
#pragma unroll
    for (int o = 16; o; o >>= 1) sum += __shfl_xor_sync(0xffffffffu, sum, o);
    __syncthreads();
    if (lane == 0) sbuf[wid] = sum;
    __syncthreads();
    if (t < 32) {
        float s = sbuf[t];
#pragma unroll
        for (int o = 16; o; o >>= 1) s += __shfl_xor_sync(0xffffffffu, s, o);
        if (t == 0) sval = s;
    }
    __syncthreads();
    float inv = 1.f / sval;
    float p0 = e0 * inv, p1 = e1 * inv, p2 = e2 * inv, p3 = e3 * inv;
    probs_out[b * 4096 + t] = p0;
    probs_out[b * 4096 + t + 1024] = p1;
    probs_out[b * 4096 + t + 2048] = p2;
    probs_out[b * 4096 + t + 3072] = p3;
    g_probs[b * 4096 + t] = p0;
    g_probs[b * 4096 + t + 1024] = p1;
    g_probs[b * 4096 + t + 2048] = p2;
    g_probs[b * 4096 + t + 3072] = p3;
}

// ---------------- zero + scatter into spectral bins ----------------
__global__ void zero_kernel(float* __restrict__ p, int n) {
    int idx = blockIdx.x * blockDim.x + threadIdx.x;
    if (idx < n) p[idx] = 0.f;
}

__global__ void scatter_kernel(const int* __restrict__ midx,
                               const float* __restrict__ inten,
                               float* __restrict__ spect) {
    int idx = blockIdx.x * blockDim.x + threadIdx.x;
    if (idx >= 8 * 4096 * 32) return;
    int b = idx >> 17;              // 4096*32 = 131072
    int s = (idx >> 5) & 4095;
    float w = inten[idx] * g_probs[b * 4096 + s];
    atomicAdd(spect + b * 65536 + midx[idx], w);
}

// ---------------- launch ----------------
extern "C" void kernel_launch(void* const* d_in, const int* in_sizes, int n_in,
                              void* d_out, int out_size) {
    const float* vf    = (const float*)d_in[0];
    const float* vmask = (const float*)d_in[1];
    const float* eoh   = (const float*)d_in[2];
    const int*   subs  = (const int*)d_in[4];
    const int*   midx  = (const int*)d_in[6];
    const float* inten = (const float*)d_in[7];
    const float* cW    = (const float*)d_in[8];
    const float* cB    = (const float*)d_in[9];
    const float* w1    = (const float*)d_in[10];
    const float* b1    = (const float*)d_in[11];
    const float* w2a   = (const float*)d_in[12];
    const float* b2a   = (const float*)d_in[13];
    const float* w2b   = (const float*)d_in[14];
    const float* b2b   = (const float*)d_in[15];
    const float* sW    = (const float*)d_in[16];
    const float* sB    = (const float*)d_in[17];
    float* out = (float*)d_out;

    int pOff = out_size - 8 * 4096;  // spect first, probs second
    size_t smem = (size_t)27168 * sizeof(float);
    cudaFuncSetAttribute(fused_main, cudaFuncAttributeMaxDynamicSharedMemorySize,
                         (int)smem);

    zero_kernel<<<(pOff + 511) / 512, 512>>>(out, pOff);
    fused_main<<<1024, TH, smem>>>(vf, vmask, eoh, subs, cW, cB, w1, b1, w2a, b2a,
                                   w2b, b2b, sW, sB);
    softmax_kernel<<<8, 1024>>>(out + pOff);
    scatter_kernel<<<2048, 512>>>(midx, inten, out);
}

// round 5
// speedup vs baseline: 1.1732x; 1.0014x over previous
#include <cuda_runtime.h>
#include <cuda_bf16.h>

#define TH 256
#define MT 32
#define PITCH 36    // 32 + 4: conflict-free, 144B col stride (16B aligned)
#define SUBP 49     // raw subset tile stride (odd -> conflict-free)

// ---------------- device globals (no allocs allowed) ----------------
__device__ float g_scores[8 * 4096];
__device__ float g_probs[8 * 4096];

typedef unsigned long long ull;

// ---------------- f32x2 helpers (sm_103a packed fp32 FMA) ----------------
__device__ __forceinline__ ull pk2(float a, float b) {
    ull r;
    asm("mov.b64 %0, {%1,%2};" : "=l"(r) : "f"(a), "f"(b));
    return r;
}
__device__ __forceinline__ void upk2(ull v, float& a, float& b) {
    asm("mov.b64 {%0,%1}, %2;" : "=f"(a), "=f"(b) : "l"(v));
}
__device__ __forceinline__ ull fma2(ull a, ull b, ull c) {
    ull d;
    asm("fma.rn.f32x2 %0, %1, %2, %3;" : "=l"(d) : "l"(a), "l"(b), "l"(c));
    return d;
}

// ---------------- row-wise instance norm over 256 dims, 32 rows ----------------
// X layout: X[k*PITCH + r], k in [0,256), r in [0,32)
__device__ __forceinline__ void rownorm(float* X, float* red1, float* red2,
                                        float* rowM, float* rowR, int tid) {
    int r = tid & 31, part = tid >> 5;  // 8 parts x 32 cols
    float s1 = 0.f, s2 = 0.f;
    const float* base = X + (part * 32) * PITCH + r;
#pragma unroll
    for (int g = 0; g < 32; g++) {
        float v = base[g * PITCH];
        s1 += v;
        s2 += v * v;
    }
    red1[part * 32 + r] = s1;
    red2[part * 32 + r] = s2;
    __syncthreads();
    if (tid < 32) {
        float a = 0.f, bq = 0.f;
#pragma unroll
        for (int p = 0; p < 8; p++) {
            a += red1[p * 32 + tid];
            bq += red2[p * 32 + tid];
        }
        float m = a * (1.f / 256.f);
        float var = bq * (1.f / 256.f) - m * m;
        rowM[tid] = m;
        rowR[tid] = rsqrtf(var + 1e-5f);
    }
    __syncthreads();
#pragma unroll
    for (int i = 0; i < 32; i++) {
        int c = (tid >> 5) + i * 8, rr = tid & 31;
        float* p = X + c * PITCH + rr;
        *p = (*p - rowM[rr]) * rowR[rr];
    }
    __syncthreads();
}

// ---------------- tiled GEMM: Y[r][c] = act( sum_k X[k][r]*W[k][c] + b[c] ) ----------------
// src/dst col-major (PITCH). Double-buffered 8-row W tiles streamed from global.
// tr = tid>>6 (rows 8*tr..8*tr+7), tc = tid&63 (cols tc+64c).
// acc packed along ROW pairs: X via LDS.128 (warp-broadcast), W scalar LDS.32.
// act: 0=relu+bias, 1=leaky(0.01)+bias, 2=scale by invs[row] (no bias/act)
__device__ __forceinline__ void mlp_gemm(const float* __restrict__ src,
                                         float* __restrict__ dst,
                                         const float* __restrict__ Wg,
                                         const float* __restrict__ bias,
                                         const float* __restrict__ invs,
                                         float* W0, float* W1, int Krows,
                                         int Ktiles, int act, int tid) {
    int tr = tid >> 6;  // 0..3
    int tc = tid & 63;
    ull acc[4][4];
#pragma unroll
    for (int i = 0; i < 4; i++)
#pragma unroll
        for (int c = 0; c < 4; c++) acc[i][c] = 0ull;

    const float4* W4 = (const float4*)Wg;
    float4 stg[2];

    // prologue: tile0 -> W0, prefetch tile1 -> regs
#pragma unroll
    for (int i = 0; i < 2; i++) {
        int f4i = tid + TH * i;
        int row = f4i >> 6;
        stg[i] = make_float4(0.f, 0.f, 0.f, 0.f);
        if (row < Krows) stg[i] = W4[row * 64 + (f4i & 63)];
    }
#pragma unroll
    for (int i = 0; i < 2; i++) ((float4*)W0)[tid + TH * i] = stg[i];
    if (Ktiles > 1) {
#pragma unroll
        for (int i = 0; i < 2; i++) {
            int f4i = tid + TH * i;
            int row = (f4i >> 6) + 8;
            stg[i] = make_float4(0.f, 0.f, 0.f, 0.f);
            if (row < Krows) stg[i] = W4[row * 64 + (f4i & 63)];
        }
    }
    __syncthreads();

    for (int kt = 0; kt < Ktiles; kt++) {
        float* cur = (kt & 1) ? W1 : W0;
        float* nxt = (kt & 1) ? W0 : W1;
        if (kt + 1 < Ktiles) {
#pragma unroll
            for (int i = 0; i < 2; i++) ((float4*)nxt)[tid + TH * i] = stg[i];
            if (kt + 2 < Ktiles) {
#pragma unroll
                for (int i = 0; i < 2; i++) {
                    int f4i = tid + TH * i;
                    int row = (f4i >> 6) + (kt + 2) * 8;
                    stg[i] = make_float4(0.f, 0.f, 0.f, 0.f);
                    if (row < Krows) stg[i] = W4[row * 64 + (f4i & 63)];
                }
            }
        }
        const float* xbase = src + (kt * 8) * PITCH + 8 * tr;
#pragma unroll
        for (int k = 0; k < 8; k++) {
            float4 xa = *(const float4*)(xbase + k * PITCH);
            float4 xb = *(const float4*)(xbase + k * PITCH + 4);
            ull xp0 = pk2(xa.x, xa.y);
            ull xp1 = pk2(xa.z, xa.w);
            ull xp2 = pk2(xb.x, xb.y);
            ull xp3 = pk2(xb.z, xb.w);
            const float* wr = cur + k * 256 + tc;
#pragma unroll
            for (int c = 0; c < 4; c++) {
                float w = wr[64 * c];
                ull wd = pk2(w, w);
                acc[0][c] = fma2(xp0, wd, acc[0][c]);
                acc[1][c] = fma2(xp1, wd, acc[1][c]);
                acc[2][c] = fma2(xp2, wd, acc[2][c]);
                acc[3][c] = fma2(xp3, wd, acc[3][c]);
            }
        }
        __syncthreads();
    }

    // epilogue
#pragma unroll
    for (int c = 0; c < 4; c++) {
        int col = tc + 64 * c;
        float y[8];
        if (act == 2) {
#pragma unroll
            for (int rp = 0; rp < 4; rp++) {
                float lo, hi;
                upk2(acc[rp][c], lo, hi);
                y[2 * rp] = lo * invs[8 * tr + 2 * rp];
                y[2 * rp + 1] = hi * invs[8 * tr + 2 * rp + 1];
            }
        } else {
            float bb = __ldg(bias + col);
#pragma unroll
            for (int rp = 0; rp < 4; rp++) {
                float lo, hi;
                upk2(acc[rp][c], lo, hi);
                lo += bb;
                hi += bb;
                if (act == 0) {
                    lo = fmaxf(lo, 0.f);
                    hi = fmaxf(hi, 0.f);
                } else {
                    lo = (lo > 0.f) ? lo : 0.01f * lo;
                    hi = (hi > 0.f) ? hi : 0.01f * hi;
                }
                y[2 * rp] = lo;
                y[2 * rp + 1] = hi;
            }
        }
        float* dcol = dst + col * PITCH + 8 * tr;
        *(float4*)dcol = make_float4(y[0], y[1], y[2], y[3]);
        *(float4*)(dcol + 4) = make_float4(y[4], y[5], y[6], y[7]);
    }
    __syncthreads();
}

// ---------------- main fused kernel: one CTA = 32 subset rows of one batch ----------------
__global__ void __launch_bounds__(TH, 2)
fused_main(const float* __restrict__ vf, const float* __restrict__ vmask,
           const float* __restrict__ eoh_g, const int* __restrict__ subs,
           const float* __restrict__ cW, const float* __restrict__ cB,
           const float* __restrict__ w1, const float* __restrict__ b1,
           const float* __restrict__ w2a, const float* __restrict__ b2a,
           const float* __restrict__ w2b, const float* __restrict__ b2b,
           const float* __restrict__ sW, const float* __restrict__ sB) {
    extern __shared__ float sm[];
    float* XA = sm;                  // 360*36 = 12960 floats
    float* XB = sm + 12960;          // 256*36 = 9216
    float* W0 = sm + 22176;          // 8*256 = 2048
    float* W1 = sm + 24224;          // 8*256 = 2048
    float* red1 = sm + 26272;        // 256
    float* red2 = sm + 26528;        // 256
    float* rowM = sm + 26784;        // 32
    float* rowR = sm + 26816;        // 32
    float* invs = sm + 26848;        // 32
    float* maskv = sm + 26880;       // 48
    float* eoh = sm + 26928;         // 240  -> total 27168 floats (106.1 KB)

    int tid = threadIdx.x;
    int b = blockIdx.x >> 7;           // 128 tiles per batch
    int s0 = (blockIdx.x & 127) * MT;

    float* SUBR = W0;  // alias: raw subset tile [32][SUBP] = 1568 <= 4096 (W0+W1)

    // ---- loads: raw subsets (contiguous 1536 ints), mask, element one-hot ----
    for (int idx = tid; idx < MT * 48; idx += TH) {
        int r = idx / 48, a = idx - r * 48;
        SUBR[r * SUBP + a] = (float)subs[(b * 4096 + s0) * 48 + idx];
    }
    if (tid < 48) maskv[tid] = vmask[b * 48 + tid];
    if (tid < 240) eoh[tid] = eoh_g[b * 240 + tid];
    __syncthreads();

    // ---- counts (160 thr), subset size (32 thr) ----
    if (tid < 160) {
        int r = tid / 5, e = tid - 5 * (tid / 5);
        float c = 0.f;
        for (int a = 0; a < 48; a++) c += SUBR[r * SUBP + a] * eoh[a * 5 + e];
        red2[tid] = c;
    } else if (tid < 192) {
        int r = tid - 160;
        float sz = 0.f;
        for (int a = 0; a < 48; a++) sz += SUBR[r * SUBP + a] * maskv[a];
        invs[r] = 1.f / (sz + 1e-4f);
    }
    __syncthreads();

    // ---- thermometer rows 0..99 ; X = (s * m^2) k-major into XB ; zero pad rows ----
    if (tid < 32) {
        int r = tid;
        float cnt[5];
#pragma unroll
        for (int e = 0; e < 5; e++) cnt[e] = red2[r * 5 + e];
#pragma unroll
        for (int e = 0; e < 5; e++)
            for (int j = 0; j < 20; j++)
                XA[(e * 20 + j) * PITCH + r] = ((float)j < cnt[e]) ? 1.f : 0.f;
    }
    for (int idx = tid; idx < 48 * 32; idx += TH) {
        int a = idx >> 5, r = idx & 31;
        float m = maskv[a];
        XB[a * PITCH + r] = SUBR[r * SUBP + a] * m * m;
    }
    if (tid >= 128 && tid < 256) {  // zero K-pad rows 356..359
        int rr = (tid - 128) & 31, row = 356 + ((tid - 128) >> 5);
        XA[row * PITCH + rr] = 0.f;
    }
    __syncthreads();

    // ---- stage A as GEMM: meanfeat = (X^T @ vf_b) * invs  -> XA rows 100..355 ----
    mlp_gemm(XB, XA + 100 * PITCH, vf + b * 48 * 256, 0, invs, W0, W1, 48, 6, 2, tid);

    rownorm(XA + 100 * PITCH, red1, red2, rowM, rowR, tid);                // subset_weighted_norm
    mlp_gemm(XA, XB, cW, cB, 0, W0, W1, 356, 45, 0, tid);                  // combine + relu
    rownorm(XB, red1, red2, rowM, rowR, tid);                              // norm_post_combine
    mlp_gemm(XB, XA, w1, b1, 0, W0, W1, 256, 32, 0, tid);                  // l1 + relu
    mlp_gemm(XA, XB, w2a, b2a, 0, W0, W1, 256, 32, 1, tid);                // l2a + leaky
    mlp_gemm(XB, XA, w2b, b2b, 0, W0, W1, 256, 32, 0, tid);                // l2b: leaky+relu == relu
    rownorm(XA, red1, red2, rowM, rowR, tid);                              // norm_pre_score

    // ---- score head ----
    {
        int r = tid & 31, part = tid >> 5;
        float s = 0.f;
#pragma unroll
        for (int gg = 0; gg < 32; gg++)
            s += XA[(part * 32 + gg) * PITCH + r] * sW[part * 32 + gg];
        red1[part * 32 + r] = s;
        __syncthreads();
        if (tid < 32) {
            float t = 0.f;
#pragma unroll
            for (int p = 0; p < 8; p++) t += red1[p * 32 + tid];
            g_scores[b * 4096 + s0 + tid] = t + sB[0];
        }
    }
}

// ---------------- per-batch softmax over 4096 scores ----------------
__global__ void softmax_kernel(float* __restrict__ probs_out) {
    __shared__ float sbuf[32];
    __shared__ float sval;
    int b = blockIdx.x, t = threadIdx.x, lane = t & 31, wid = t >> 5;
    const float* sc = g_scores + b * 4096;
    float v0 = sc[t], v1 = sc[t + 1024], v2 = sc[t + 2048], v3 = sc[t + 3072];
    float mx = fmaxf(fmaxf(v0, v1), fmaxf(v2, v3));
#pragma unroll
    for (int o = 16; o; o >>= 1) mx = fmaxf(mx, __shfl_xor_sync(0xffffffffu, mx, o));
    if (lane == 0) sbuf[wid] = mx;
    __syncthreads();
    if (t < 32) {
        float m = sbuf[t];
#pragma unroll
        for (int o = 16; o; o >>= 1) m = fmaxf(m, __shfl_xor_sync(0xffffffffu, m, o));
        if (t == 0) sval = m;
    }
    __syncthreads();
    mx = sval;
    float e0 = expf(v0 - mx), e1 = expf(v1 - mx), e2 = expf(v2 - mx), e3 = expf(v3 - mx);
    float sum = e0 + e1 + e2 + e3;
#pragma unroll
    for (int o = 16; o; o >>= 1) sum += __shfl_xor_sync(0xffffffffu, sum, o);
    __syncthreads();
    if (lane == 0) sbuf[wid] = sum;
    __syncthreads();
    if (t < 32) {
        float s = sbuf[t];
#pragma unroll
        for (int o = 16; o; o >>= 1) s += __shfl_xor_sync(0xffffffffu, s, o);
        if (t == 0) sval = s;
    }
    __syncthreads();
    float inv = 1.f / sval;
    float p0 = e0 * inv, p1 = e1 * inv, p2 = e2 * inv, p3 = e3 * inv;
    probs_out[b * 4096 + t] = p0;
    probs_out[b * 4096 + t + 1024] = p1;
    probs_out[b * 4096 + t + 2048] = p2;
    probs_out[b * 4096 + t + 3072] = p3;
    g_probs[b * 4096 + t] = p0;
    g_probs[b * 4096 + t + 1024] = p1;
    g_probs[b * 4096 + t + 2048] = p2;
    g_probs[b * 4096 + t + 3072] = p3;
}

// ---------------- zero + scatter into spectral bins ----------------
__global__ void zero_kernel(float* __restrict__ p, int n) {
    int idx = blockIdx.x * blockDim.x + threadIdx.x;
    if (idx < n) p[idx] = 0.f;
}

__global__ void scatter_kernel(const int* __restrict__ midx,
                               const float* __restrict__ inten,
                               float* __restrict__ spect) {
    int idx = blockIdx.x * blockDim.x + threadIdx.x;
    if (idx >= 8 * 4096 * 32) return;
    int b = idx >> 17;              // 4096*32 = 131072
    int s = (idx >> 5) & 4095;
    float w = inten[idx] * g_probs[b * 4096 + s];
    atomicAdd(spect + b * 65536 + midx[idx], w);
}

// ---------------- launch ----------------
extern "C" void kernel_launch(void* const* d_in, const int* in_sizes, int n_in,
                              void* d_out, int out_size) {
    const float* vf    = (const float*)d_in[0];
    const float* vmask = (const float*)d_in[1];
    const float* eoh   = (const float*)d_in[2];
    const int*   subs  = (const int*)d_in[4];
    const int*   midx  = (const int*)d_in[6];
    const float* inten = (const float*)d_in[7];
    const float* cW    = (const float*)d_in[8];
    const float* cB    = (const float*)d_in[9];
    const float* w1    = (const float*)d_in[10];
    const float* b1    = (const float*)d_in[11];
    const float* w2a   = (const float*)d_in[12];
    const float* b2a   = (const float*)d_in[13];
    const float* w2b   = (const float*)d_in[14];
    const float* b2b   = (const float*)d_in[15];
    const float* sW    = (const float*)d_in[16];
    const float* sB    = (const float*)d_in[17];
    float* out = (float*)d_out;

    int pOff = out_size - 8 * 4096;  // spect first, probs second
    size_t smem = (size_t)27168 * sizeof(float);
    cudaFuncSetAttribute(fused_main, cudaFuncAttributeMaxDynamicSharedMemorySize,
                         (int)smem);

    zero_kernel<<<(pOff + 511) / 512, 512>>>(out, pOff);
    fused_main<<<1024, TH, smem>>>(vf, vmask, eoh, subs, cW, cB, w1, b1, w2a, b2a,
                                   w2b, b2b, sW, sB);
    softmax_kernel<<<8, 1024>>>(out + pOff);
    scatter_kernel<<<2048, 512>>>(midx, inten, out);
}